// round 14
// baseline (speedup 1.0000x reference)
#include <cuda_runtime.h>
#include <cstdint>

#define NIMG 32          // 16 ref + 16 tgt
#define B_   16
#define H_   512
#define W_   512
#define HW_  (H_*W_)

// ---------------- scratch (device globals: allocation-free) ----------------
__device__ unsigned char g_ed [NIMG * HW_];   // 8.4 MB  (bit0 = e, bit1 = d)
__device__ float         g_acc[NIMG * 4];     // zero-init at load; re-zeroed by epilogue

// ---------------- K1: fully fused row-streaming kernel (2 barriers/step) ----
// Block: 128 threads, 4 cols/thread = full 512-px width; strip of 32 output
// rows. Dilation is lagged one step behind Sobel so each step needs only TWO
// __syncthreads:
//   P0: lum row store + rgb prefetch; consume v(i-1) -> ed row rv=y0-10+i;
//       vertical vs update; publish shuffle halos.        | bar1
//   P1: Sobel row rE=y0-7+i; write v(i) to vbuf; horizontal 7-tap + masked
//       variance accumulate for output row rv-3.          | bar2
#define STRIP  32
#define NSTEPS (STRIP + 13)    // 45 (12-row pipeline + 1 extra lag step)
#define LRING  12
#define LPITCH 528     // cols -4..515 live at idx 0..519 (pads zero), stride 528

__global__ __launch_bounds__(128) void k_fused(const float* __restrict__ ref,
                                               const float* __restrict__ tgt)
{
    const int img = blockIdx.y;
    const int y0  = blockIdx.x * STRIP;
    const int t   = threadIdx.x;
    const int w   = t >> 5, l = t & 31;
    const int c0  = t * 4;

    const float* src = (img < B_) ? (ref + (size_t)img * 3 * HW_)
                                  : (tgt + (size_t)(img - B_) * 3 * HW_);
    unsigned char* edout = g_ed + (size_t)img * HW_;

    __shared__ float    slum[LRING][LPITCH];
    __shared__ unsigned vbuf[2][132];          // idx 1+t; [0] and [129] stay 0
    __shared__ float    sufB[2][4][6][3];
    __shared__ float    preB[2][4][6][3];

    // zero smem (pads + never-written halo slots must be 0, not garbage/NaN)
    for (int k = t; k < LRING * LPITCH; k += 128) ((float*)slum)[k] = 0.f;
    for (int k = t; k < 2 * 132; k += 128) ((unsigned*)vbuf)[k] = 0u;
    __syncthreads();

    // E shift ring (newest = e4_4 = row rE of the last completed Sobel)
    unsigned e4_0 = 0, e4_1 = 0, e4_2 = 0, e4_3 = 0, e4_4 = 0;
    unsigned vprev = 0;   // v row computed at P1 of previous step (own cols)
    // ed shift ring (newest = edr6 = row rv); OOB rows = 0x03 per byte
    unsigned edr0 = 0x03030303u, edr1 = 0x03030303u, edr2 = 0x03030303u,
             edr3 = 0x03030303u, edr4 = 0x03030303u, edr5 = 0x03030303u,
             edr6 = 0x03030303u;

    float vs[6][4];
#pragma unroll
    for (int q = 0; q < 6; q++)
#pragma unroll
        for (int c = 0; c < 4; c++) vs[q][c] = 0.f;

    float accVp = 0.f, accNp = 0.f, accVb = 0.f, accNb = 0.f;

    // prefetch rgb row for step 0 (rl = y0-6)
    float4 pr, pg, pb;
    bool pvalid;
    {
        int rl0 = y0 - 6;
        pvalid = (rl0 >= 0 && rl0 < H_);
        if (pvalid) {
            pr = *(const float4*)(src + rl0 * W_ + c0);
            pg = *(const float4*)(src + HW_ + rl0 * W_ + c0);
            pb = *(const float4*)(src + 2 * HW_ + rl0 * W_ + c0);
        }
    }

    int cur = 0;   // lum ring write slot for step i (row rl = y0-6+i)

#pragma unroll 1
    for (int i = 0; i < NSTEPS; i++) {
        // ================= P0 =================
        float4 lumv = make_float4(0.f, 0.f, 0.f, 0.f);
        if (pvalid) {
            lumv.x = 0.299f * pr.x + 0.587f * pg.x + 0.114f * pb.x;
            lumv.y = 0.299f * pr.y + 0.587f * pg.y + 0.114f * pb.y;
            lumv.z = 0.299f * pr.z + 0.587f * pg.z + 0.114f * pb.z;
            lumv.w = 0.299f * pr.w + 0.587f * pg.w + 0.114f * pb.w;
        }
        *(float4*)&slum[cur][4 + c0] = lumv;

        {   // prefetch next rgb row
            int rln = y0 - 5 + i;
            pvalid = (i < NSTEPS - 1) && (rln >= 0) && (rln < H_);
            if (pvalid) {
                pr = *(const float4*)(src + rln * W_ + c0);
                pg = *(const float4*)(src + HW_ + rln * W_ + c0);
                pb = *(const float4*)(src + 2 * HW_ + rln * W_ + c0);
            }
        }

        if (i >= 7) {
            const int iv = i - 7;
            const int rv = y0 - 3 + iv;        // = y0 - 10 + i

            // ---- dilation for row rv, consuming v(i-1) ----
            unsigned v  = vprev;                       // own columns, register
            unsigned vL = vbuf[(i - 1) & 1][t];        // left neighbor chunk
            unsigned vR = vbuf[(i - 1) & 1][2 + t];    // right neighbor chunk
            unsigned d4 = v
                        | ((vL >> 16) | (v << 16))
                        | ((vL >> 24) | (v << 8))
                        | ((v >> 8)   | (vR << 24))
                        | ((v >> 16)  | (vR << 16));
            unsigned ed4 = e4_2 | (d4 << 1);   // pre-shift ring: e4_2 = E(rv)

            if (iv >= 3 && iv <= STRIP + 2)
                *(unsigned*)(edout + rv * W_ + c0) = ed4;
            if (rv < 0 || rv >= H_) ed4 = 0x03030303u; // OOB: both masks 0

            // ---- variance vertical update (lum rows rv = rl-4, rv-7 = rl-11) --
            int sn = cur - 4;  if (sn < 0) sn += LRING;
            int so = cur - 11; if (so < 0) so += LRING;
            float4 xv  = *(const float4*)&slum[sn][4 + c0];
            float4 xo4 = *(const float4*)&slum[so][4 + c0];
#pragma unroll
            for (int c = 0; c < 4; c++) {
                unsigned bn = (ed4  >> (8 * c)) & 3u;
                unsigned bo = (edr0 >> (8 * c)) & 3u;
                float xn  = (&xv.x)[c];
                float xo  = (&xo4.x)[c];
                float mpn = (bn == 2u) ? 1.f : 0.f;
                float mbn = (bn == 0u) ? 1.f : 0.f;
                float mpo = (bo == 2u) ? 1.f : 0.f;
                float mbo = (bo == 0u) ? 1.f : 0.f;
                vs[0][c] += mpn - mpo;
                vs[1][c] += xn * mpn - xo * mpo;
                vs[2][c] += xn * xn * mpn - xo * xo * mpo;
                vs[3][c] += mbn - mbo;
                vs[4][c] += xn * mbn - xo * mbo;
                vs[5][c] += xn * xn * mbn - xo * xo * mbo;
            }
            edr0 = edr1; edr1 = edr2; edr2 = edr3;
            edr3 = edr4; edr4 = edr5; edr5 = edr6; edr6 = ed4;

            // ---- publish warp-boundary halos (consumed in P1 after bar1) ----
            if (iv >= 6) {
                const int par = iv & 1;
                if (l == 31) {
#pragma unroll
                    for (int q = 0; q < 6; q++) {
                        sufB[par][w][q][0] = vs[q][1] + vs[q][2] + vs[q][3];
                        sufB[par][w][q][1] = vs[q][2] + vs[q][3];
                        sufB[par][w][q][2] = vs[q][3];
                    }
                }
                if (l == 0) {
#pragma unroll
                    for (int q = 0; q < 6; q++) {
                        preB[par][w][q][0] = vs[q][0];
                        preB[par][w][q][1] = vs[q][0] + vs[q][1];
                        preB[par][w][q][2] = vs[q][0] + vs[q][1] + vs[q][2];
                    }
                }
            }
        }
        __syncthreads();   // bar1: lum[cur] + halos visible; vbuf read done

        // ================= P1 =================
        // ---- Sobel E row rE = y0-7+i ----
        unsigned epack = 0;
        {
            const int rE = y0 - 7 + i;
            if (i >= 2 && rE >= 0 && rE < H_) {
                int sa = cur - 2; if (sa < 0) sa += LRING;
                int sb = cur - 1; if (sb < 0) sb += LRING;
                float A[6], Bv[6], D[6];
                *(float4*)&A[1]  = *(const float4*)&slum[sa][4 + c0];
                A[0]  = slum[sa][3 + c0];  A[5]  = slum[sa][8 + c0];
                *(float4*)&Bv[1] = *(const float4*)&slum[sb][4 + c0];
                Bv[0] = slum[sb][3 + c0];  Bv[5] = slum[sb][8 + c0];
                *(float4*)&D[1]  = *(const float4*)&slum[cur][4 + c0];
                D[0]  = slum[cur][3 + c0]; D[5]  = slum[cur][8 + c0];
#pragma unroll
                for (int c = 0; c < 4; c++) {
                    float gx = (A[c+2] - A[c]) + 2.f * (Bv[c+2] - Bv[c]) + (D[c+2] - D[c]);
                    float gy = (D[c]   - A[c]) + 2.f * (D[c+1] - A[c+1]) + (D[c+2] - A[c+2]);
                    float g2 = gx * gx + gy * gy + 1e-12f;   // sqrt>0.1 <=> >0.01
                    if (g2 > 0.01f) epack |= 1u << (8 * c);
                }
            }
        }
        e4_0 = e4_1; e4_1 = e4_2; e4_2 = e4_3; e4_3 = e4_4; e4_4 = epack;

        // ---- v row for next step's dilation ----
        vprev = e4_0 | e4_1 | e4_2 | e4_3 | e4_4;
        vbuf[i & 1][1 + t] = vprev;

        // ---- horizontal 7-tap + masked accumulate (output row rv-3) ----
        if (i >= 13) {                       // iv >= 6
            const int par = (i - 7) & 1;
            unsigned edc = edr3;             // center row rv-3
#pragma unroll
            for (int g = 0; g < 2; g++) {
                float Wn[3][4];
#pragma unroll
                for (int qq = 0; qq < 3; qq++) {
                    const int q = 3 * g + qq;
                    float p0 = vs[q][0];
                    float p1 = p0 + vs[q][1];
                    float p2 = p1 + vs[q][2];
                    float T  = p2 + vs[q][3];
                    float s1 = T - p0, s2 = T - p1, s3 = T - p2;
                    float ls1 = __shfl_up_sync(0xffffffffu, s1, 1);
                    float ls2 = __shfl_up_sync(0xffffffffu, s2, 1);
                    float ls3 = __shfl_up_sync(0xffffffffu, s3, 1);
                    float rp0 = __shfl_down_sync(0xffffffffu, p0, 1);
                    float rp1 = __shfl_down_sync(0xffffffffu, p1, 1);
                    float rp2 = __shfl_down_sync(0xffffffffu, p2, 1);
                    if (l == 0) {
                        ls1 = (w > 0) ? sufB[par][w - 1][q][0] : 0.f;
                        ls2 = (w > 0) ? sufB[par][w - 1][q][1] : 0.f;
                        ls3 = (w > 0) ? sufB[par][w - 1][q][2] : 0.f;
                    }
                    if (l == 31) {
                        rp0 = (w < 3) ? preB[par][w + 1][q][0] : 0.f;
                        rp1 = (w < 3) ? preB[par][w + 1][q][1] : 0.f;
                        rp2 = (w < 3) ? preB[par][w + 1][q][2] : 0.f;
                    }
                    Wn[qq][0] = ls1 + T;
                    Wn[qq][1] = ls2 + T + rp0;
                    Wn[qq][2] = ls3 + T + rp1;
                    Wn[qq][3] = T + rp2;
                }
                float aV = 0.f, aN = 0.f;
#pragma unroll
                for (int c = 0; c < 4; c++) {
                    float cnt = fmaxf(Wn[0][c], 1.f);
                    float rcn = __fdividef(1.f, cnt);
                    float mu  = Wn[1][c] * rcn;
                    float var = fmaxf(Wn[2][c] * rcn - mu * mu, 0.f);
                    unsigned bc = (edc >> (8 * c)) & 3u;
                    float m = (g == 0) ? ((bc == 2u) ? 1.f : 0.f)
                                       : ((bc == 0u) ? 1.f : 0.f);
                    aV += m * var; aN += m;
                }
                if (g == 0) { accVp += aV; accNp += aN; }
                else        { accVb += aV; accNb += aN; }
            }
        }
        __syncthreads();   // bar2: vbuf write visible before next P0 read

        cur++; if (cur == LRING) cur = 0;
    }

    // ---- warp reduce + one atomic per warp per scalar ----
#pragma unroll
    for (int off = 16; off > 0; off >>= 1) {
        accVp += __shfl_down_sync(0xffffffffu, accVp, off);
        accNp += __shfl_down_sync(0xffffffffu, accNp, off);
        accVb += __shfl_down_sync(0xffffffffu, accVb, off);
        accNb += __shfl_down_sync(0xffffffffu, accNb, off);
    }
    if (l == 0) {
        atomicAdd(&g_acc[img * 4 + 0], accVp);
        atomicAdd(&g_acc[img * 4 + 1], accNp);
        atomicAdd(&g_acc[img * 4 + 2], accVb);
        atomicAdd(&g_acc[img * 4 + 3], accNb);
    }
}

// ---------------- K2: flags + output = clip(ringing_tgt - ringing_ref, 0) ---
__global__ void k_output(float* __restrict__ out)
{
    int idx = blockIdx.x * blockDim.x + threadIdx.x;
    const int n4 = B_ * HW_ / 4;
    if (idx >= n4) return;
    int b  = idx / (HW_ / 4);
    int p4 = idx % (HW_ / 4);

    float vpr = g_acc[b * 4 + 0],        npr = g_acc[b * 4 + 1];
    float vbr = g_acc[b * 4 + 2],        nbr = g_acc[b * 4 + 3];
    float vpt = g_acc[(b + B_) * 4 + 0], npt = g_acc[(b + B_) * 4 + 1];
    float vbt = g_acc[(b + B_) * 4 + 2], nbt = g_acc[(b + B_) * 4 + 3];
    float fr = ((vpr / fmaxf(npr, 1.f)) / (vbr / fmaxf(nbr, 1.f) + 1e-12f) > 2.0f) ? 1.f : 0.f;
    float ft = ((vpt / fmaxf(npt, 1.f)) / (vbt / fmaxf(nbt, 1.f) + 1e-12f) > 2.0f) ? 1.f : 0.f;

    const uchar4* edr4 = (const uchar4*)(g_ed + (size_t)b * HW_);
    const uchar4* edt4 = (const uchar4*)(g_ed + (size_t)(b + B_) * HW_);
    uchar4 r4 = edr4[p4], t4 = edt4[p4];

    // byte==2 (d=1,e=0) <=> pixel in M_prox
    float4 o;
    o.x = fmaxf((t4.x == 2 ? ft : 0.f) - (r4.x == 2 ? fr : 0.f), 0.f);
    o.y = fmaxf((t4.y == 2 ? ft : 0.f) - (r4.y == 2 ? fr : 0.f), 0.f);
    o.z = fmaxf((t4.z == 2 ? ft : 0.f) - (r4.z == 2 ? fr : 0.f), 0.f);
    o.w = fmaxf((t4.w == 2 ? ft : 0.f) - (r4.w == 2 ? fr : 0.f), 0.f);
    ((float4*)out)[idx] = o;
}

// ---------------- K3: epilogue — re-zero g_acc for the next (graph) call ----
__global__ void k_zero_acc()
{
    if (threadIdx.x < NIMG * 4) g_acc[threadIdx.x] = 0.f;
}

// ---------------- launch ----------------
extern "C" void kernel_launch(void* const* d_in, const int* in_sizes, int n_in,
                              void* d_out, int out_size)
{
    const float* ref = (const float*)d_in[0];
    const float* tgt = (const float*)d_in[1];

    k_fused<<<dim3(H_ / STRIP, NIMG), 128>>>(ref, tgt);

    const int n4 = B_ * HW_ / 4;
    k_output<<<(n4 + 255) / 256, 256>>>((float*)d_out);

    k_zero_acc<<<1, 128>>>();
}